// round 14
// baseline (speedup 1.0000x reference)
#include <cuda_runtime.h>
#include <cuda_fp16.h>
#include <cstdint>
#include <math.h>

// Problem constants: q,k,v : [B, S, D] float32
#define BATCH 8
#define SEQ   2048
#define DIM   512
#define NROWS (BATCH * SEQ)        // 16384
#define NTILE 8                    // SEQ / 256 (GEMM1 n-tiles per row)

// ---------------------------------------------------------------------------
// Scratch (__device__ globals; no allocation allowed)
// ---------------------------------------------------------------------------
__device__ __half g_qh[(size_t)BATCH * SEQ * DIM];   // Q in fp16
__device__ __half g_kh[(size_t)BATCH * SEQ * DIM];   // K in fp16
__device__ __half g_vt[(size_t)BATCH * DIM * SEQ];   // V transposed (K-major), fp16
__device__ __half g_wh[(size_t)BATCH * SEQ * SEQ];   // E = exp(scores), fp16
__device__ float  g_part[(size_t)NTILE * NROWS];     // per-CTA row partial sums

__device__ __forceinline__ void ldsm_x4(uint32_t r[4], uint32_t addr) {
    asm volatile("ldmatrix.sync.aligned.m8n8.x4.shared.b16 {%0,%1,%2,%3}, [%4];"
                 : "=r"(r[0]), "=r"(r[1]), "=r"(r[2]), "=r"(r[3]) : "r"(addr));
}

// ---------------------------------------------------------------------------
// fp16 warp-MMA GEMM:  C[b] = A[b] (MxK, K-major) * B[b]^T (NxK, K-major)
// BM=128 fixed; TBN/TNTHR templated. BK=64 halves (128B rows, XOR swizzle),
// 3-stage cp.async, warp tile 64x32 (wm = wid&1, wn = wid>>1).
//
// Heterogeneous peer-CTA grids (same kernel => same resource shape => true
// co-residency; the ONLY overlap mechanism that works on this part):
// EXP_OUT=true  (GEMM1): grid.x = SEQ/TBN + 1.
//   x <  SEQ/TBN : E = exp(alpha*acc) -> fp16, row partial sums to part.
//   x == SEQ/TBN : TRANSPOSE peers — V[bz, m0..m0+128, :] -> Vt[bz, :, ...]
//                  (fp32->fp16), hidden in GEMM1's ~7-wave tensor grid.
// EXP_OUT=false (GEMM2): grid.x = DIM/TBN + 2.
//   x <  DIM/TBN : out = (E V) * inv (inv recomputed from part — deterministic).
//   x >= DIM/TBN : NORMALIZE peers — 64 rows each of fp32 W = E * inv.
// ---------------------------------------------------------------------------
#define NSTG 3

template <int TBN, int TNTHR, int MINB, bool EXP_OUT>
__global__ __launch_bounds__(TNTHR, MINB)
void gemm_h(const __half* __restrict__ A, const __half* __restrict__ B,
            void* __restrict__ Cv, float* __restrict__ part,
            float* __restrict__ Wout,
            const float* __restrict__ Vsrc, __half* __restrict__ VtDst,
            int M, int N, int Kd, float alpha)
{
    constexpr int A_BYTES = 128 * 128;
    constexpr int B_BYTES = TBN * 128;
    constexpr int STAGE_BYTES = A_BYTES + B_BYTES;
    constexpr int AI = (128 * 8) / TNTHR;
    constexpr int BI = (TBN * 8) / TNTHR;
    constexpr int NWN = TNTHR / 64;          // warps in n-direction

    extern __shared__ char smem[];
    const uint32_t smem_b = (uint32_t)__cvta_generic_to_shared(smem);

    const int tid = threadIdx.x;
    const int bz  = blockIdx.z;
    const int m0  = blockIdx.y * 128;
    const size_t grow0 = (size_t)bz * M + m0;       // first global row

    // ---- Transpose peer path (GEMM1 only, last x) ----
    if (EXP_OUT && blockIdx.x == gridDim.x - 1) {
        // V[bz, m0..m0+128, 0..DIM) -> Vt[bz, 0..DIM, m0..m0+128), fp16.
        // 512 threads = 2 groups x 256; each group owns one 32x32 tile/iter.
        float* tile = reinterpret_cast<float*>(smem) + (tid >> 8) * (32 * 33);
        const int tid2 = tid & 255;
        const int xx = tid2 & 31;
        const int yy = tid2 >> 5;              // 0..7
        const float* Vb = Vsrc + (size_t)bz * SEQ * DIM;
        __half*      Tb = VtDst + (size_t)bz * DIM * SEQ;
        for (int it = 0; it < 32; it++) {
            const int tt = it * 2 + (tid >> 8);   // tile id 0..63
            const int s0t = m0 + (tt >> 4) * 32;
            const int d0t = (tt & 15) * 32;
            __syncthreads();
#pragma unroll
            for (int i = 0; i < 32; i += 8)
                tile[(yy + i) * 33 + xx] =
                    Vb[(size_t)(s0t + yy + i) * DIM + d0t + xx];
            __syncthreads();
#pragma unroll
            for (int i = 0; i < 32; i += 8)
                Tb[(size_t)(d0t + yy + i) * SEQ + s0t + xx] =
                    __float2half_rn(tile[xx * 33 + yy + i]);
        }
        return;
    }

    // ---- Normalize peer path (GEMM2 only, x >= N/TBN) ----
    if (!EXP_OUT && blockIdx.x >= N / TBN) {
        const int half = blockIdx.x - N / TBN;     // 0 or 1
        const size_t rbase = grow0 + half * 64;
        __shared__ float s_inv2[64];
        if (tid < 64) {
            float s = 0.0f;
#pragma unroll
            for (int j = 0; j < NTILE; j++)
                s += __ldg(part + (size_t)j * NROWS + rbase + tid);
            s_inv2[tid] = 1.0f / s;
        }
        __syncthreads();
        // W[row] = E[row] * inv for 64 rows (E row len = Kd = SEQ here).
#pragma unroll 2
        for (int ch = tid; ch < 64 * 256; ch += TNTHR) {
            const int r  = ch >> 8;          // 0..63
            const int cc = ch & 255;         // 16B chunk in row
            const float iv = s_inv2[r];
            float4 raw = __ldg(reinterpret_cast<const float4*>(
                                   A + (rbase + r) * (size_t)Kd) + cc);
            float2 p0 = __half22float2(*reinterpret_cast<__half2*>(&raw.x));
            float2 p1 = __half22float2(*reinterpret_cast<__half2*>(&raw.y));
            float2 p2 = __half22float2(*reinterpret_cast<__half2*>(&raw.z));
            float2 p3 = __half22float2(*reinterpret_cast<__half2*>(&raw.w));
            float4 o0 = make_float4(p0.x * iv, p0.y * iv, p1.x * iv, p1.y * iv);
            float4 o1 = make_float4(p2.x * iv, p2.y * iv, p3.x * iv, p3.y * iv);
            float* pw = Wout + (rbase + r) * (size_t)Kd + cc * 8;
            *reinterpret_cast<float4*>(pw)     = o0;
            *reinterpret_cast<float4*>(pw + 4) = o1;
        }
        return;
    }

    const int wid  = tid >> 5;
    const int lane = tid & 31;
    const int g    = lane >> 2;
    const int tg   = lane & 3;
    const int lr   = lane & 15;
    const int lc   = lane >> 4;

    const int wm = wid & 1;
    const int wn = wid >> 1;

    const int n0 = blockIdx.x * TBN;
    const __half* Ab = A + (size_t)bz * M * Kd;
    const __half* Bb = B + (size_t)bz * N * Kd;

    float acc[4][4][4];
#pragma unroll
    for (int i = 0; i < 4; i++)
#pragma unroll
        for (int j = 0; j < 4; j++)
#pragma unroll
            for (int r = 0; r < 4; r++)
                acc[i][j][r] = 0.0f;

    const int T = Kd / 64;

    auto load_stage = [&](int buf, int kt) {
        const int k0 = kt * 64;
        const uint32_t ab = smem_b + (uint32_t)buf * STAGE_BYTES;
        const uint32_t bb = ab + A_BYTES;
#pragma unroll
        for (int i = 0; i < AI; i++) {
            int idx = tid + i * TNTHR;
            int row = idx >> 3;
            int c   = idx & 7;
            uint32_t d = ab + (uint32_t)(row * 128 + ((c ^ (row & 7)) << 4));
            const __half* s = Ab + (size_t)(m0 + row) * Kd + k0 + c * 8;
            asm volatile("cp.async.cg.shared.global [%0], [%1], 16;" :: "r"(d), "l"(s));
        }
#pragma unroll
        for (int i = 0; i < BI; i++) {
            int idx = tid + i * TNTHR;
            int row = idx >> 3;
            int c   = idx & 7;
            uint32_t d = bb + (uint32_t)(row * 128 + ((c ^ (row & 7)) << 4));
            const __half* s = Bb + (size_t)(n0 + row) * Kd + k0 + c * 8;
            asm volatile("cp.async.cg.shared.global [%0], [%1], 16;" :: "r"(d), "l"(s));
        }
    };

#pragma unroll
    for (int s = 0; s < NSTG - 1; s++) {
        load_stage(s, s);
        asm volatile("cp.async.commit_group;" ::: "memory");
    }

    int cbuf = 0;
    int lbuf = NSTG - 1;
    for (int t = 0; t < T; t++) {
        asm volatile("cp.async.wait_group %0;" :: "n"(NSTG - 2) : "memory");
        __syncthreads();

        const int tn = t + NSTG - 1;
        if (tn < T) load_stage(lbuf, tn);
        asm volatile("cp.async.commit_group;" ::: "memory");
        lbuf = (lbuf + 1 == NSTG) ? 0 : lbuf + 1;

        const uint32_t ab = smem_b + (uint32_t)cbuf * STAGE_BYTES;
        const uint32_t bb = ab + A_BYTES;
        cbuf = (cbuf + 1 == NSTG) ? 0 : cbuf + 1;

#pragma unroll
        for (int ks = 0; ks < 4; ks++) {
            const int c = ks * 2 + lc;
            uint32_t a[4][4], b[2][4];
#pragma unroll
            for (int mt = 0; mt < 4; mt++) {
                int r = wm * 64 + mt * 16 + lr;
                ldsm_x4(a[mt], ab + (uint32_t)(r * 128 + ((c ^ (r & 7)) << 4)));
            }
#pragma unroll
            for (int pr = 0; pr < 2; pr++) {
                int r = wn * 32 + pr * 16 + lr;
                ldsm_x4(b[pr], bb + (uint32_t)(r * 128 + ((c ^ (r & 7)) << 4)));
            }
#pragma unroll
            for (int mt = 0; mt < 4; mt++)
#pragma unroll
                for (int nt = 0; nt < 4; nt++) {
                    const int pr = nt >> 1, od = nt & 1;
                    asm volatile(
                        "mma.sync.aligned.m16n8k16.row.col.f32.f16.f16.f32 "
                        "{%0,%1,%2,%3}, {%4,%5,%6,%7}, {%8,%9}, {%0,%1,%2,%3};"
                        : "+f"(acc[mt][nt][0]), "+f"(acc[mt][nt][1]),
                          "+f"(acc[mt][nt][2]), "+f"(acc[mt][nt][3])
                        : "r"(a[mt][0]), "r"(a[mt][1]), "r"(a[mt][2]), "r"(a[mt][3]),
                          "r"(b[pr][od]), "r"(b[pr][od + 2]));
                }
        }
    }

    if (EXP_OUT) {
        // ---- Epilogue: E = exp(alpha*acc) -> fp16, + row partial sums ----
        __half* Cb = (__half*)Cv + (size_t)bz * M * N;
        __syncthreads();                          // stage smem now dead
        float* ssum = reinterpret_cast<float*>(smem);   // [128][NWN]
#pragma unroll
        for (int mt = 0; mt < 4; mt++) {
            const int row = m0 + wm * 64 + mt * 16 + g;
            float s0 = 0.0f, s1 = 0.0f;
#pragma unroll
            for (int nt = 0; nt < 4; nt++) {
                const int col = n0 + wn * 32 + nt * 8 + 2 * tg;
                float e0 = __expf(acc[mt][nt][0] * alpha);
                float e1 = __expf(acc[mt][nt][1] * alpha);
                float e2 = __expf(acc[mt][nt][2] * alpha);
                float e3 = __expf(acc[mt][nt][3] * alpha);
                *reinterpret_cast<__half2*>(Cb + (size_t)row * N + col) =
                    __float22half2_rn(make_float2(e0, e1));
                *reinterpret_cast<__half2*>(Cb + (size_t)(row + 8) * N + col) =
                    __float22half2_rn(make_float2(e2, e3));
                s0 += e0 + e1;
                s1 += e2 + e3;
            }
            s0 += __shfl_xor_sync(0xffffffffu, s0, 1);
            s0 += __shfl_xor_sync(0xffffffffu, s0, 2);
            s1 += __shfl_xor_sync(0xffffffffu, s1, 1);
            s1 += __shfl_xor_sync(0xffffffffu, s1, 2);
            if (tg == 0) {
                const int rl = wm * 64 + mt * 16 + g;
                ssum[rl * NWN + wn]       = s0;
                ssum[(rl + 8) * NWN + wn] = s1;
            }
        }
        __syncthreads();
        if (tid < 128) {
            float tsum = 0.0f;
#pragma unroll
            for (int j = 0; j < NWN; j++) tsum += ssum[tid * NWN + j];
            part[(size_t)blockIdx.x * NROWS + grow0 + tid] = tsum;
        }
    } else {
        // ---- Epilogue: inv from partials (deterministic), then fp32 out ----
        __syncthreads();                          // stage smem now dead
        float* s_inv = reinterpret_cast<float*>(smem);   // [128]
        if (tid < 128) {
            float s = 0.0f;
#pragma unroll
            for (int j = 0; j < NTILE; j++)
                s += __ldg(part + (size_t)j * NROWS + grow0 + tid);
            s_inv[tid] = 1.0f / s;
        }
        __syncthreads();

        float* Cb = (float*)Cv + (size_t)bz * M * N;
#pragma unroll
        for (int mt = 0; mt < 4; mt++) {
            const int rl = wm * 64 + mt * 16 + g;
            const int row = m0 + rl;
            const float i0 = s_inv[rl] * alpha;
            const float i1 = s_inv[rl + 8] * alpha;
#pragma unroll
            for (int nt = 0; nt < 4; nt++) {
                const int col = n0 + wn * 32 + nt * 8 + 2 * tg;
                float2 lo, hi;
                lo.x = acc[mt][nt][0] * i0; lo.y = acc[mt][nt][1] * i0;
                hi.x = acc[mt][nt][2] * i1; hi.y = acc[mt][nt][3] * i1;
                *reinterpret_cast<float2*>(Cb + (size_t)row * N + col)       = lo;
                *reinterpret_cast<float2*>(Cb + (size_t)(row + 8) * N + col) = hi;
            }
        }
    }
}

// ---------------------------------------------------------------------------
// Pre-pass: fp32 -> fp16 for Q and K in one launch (blockIdx.y selects input)
// ---------------------------------------------------------------------------
__global__ __launch_bounds__(256)
void to_half_qk_kernel(const float4* __restrict__ q, const float4* __restrict__ k,
                       __half2* __restrict__ qh, __half2* __restrict__ kh, int n4)
{
    int i = blockIdx.x * blockDim.x + threadIdx.x;
    if (i >= n4) return;
    const float4* in  = blockIdx.y ? k  : q;
    __half2*      out = blockIdx.y ? kh : qh;
    float4 v = in[i];
    out[2 * i]     = __float22half2_rn(make_float2(v.x, v.y));
    out[2 * i + 1] = __float22half2_rn(make_float2(v.z, v.w));
}

// ---------------------------------------------------------------------------
// Launch: out = [output (B*S*D) | attention_weights (B*S*S)]
// ---------------------------------------------------------------------------
extern "C" void kernel_launch(void* const* d_in, const int* in_sizes, int n_in,
                              void* d_out, int out_size)
{
    (void)in_sizes; (void)n_in; (void)out_size;
    const float* q = (const float*)d_in[0];
    const float* k = (const float*)d_in[1];
    const float* v = (const float*)d_in[2];
    float* out = (float*)d_out;
    float* w   = out + (size_t)BATCH * SEQ * DIM;   // fp32 weights region

    __half *qh, *kh, *vt, *wh;
    float *part;
    cudaGetSymbolAddress((void**)&qh, g_qh);
    cudaGetSymbolAddress((void**)&kh, g_kh);
    cudaGetSymbolAddress((void**)&vt, g_vt);
    cudaGetSymbolAddress((void**)&wh, g_wh);
    cudaGetSymbolAddress((void**)&part, g_part);

    const int smem1 = NSTG * (128 + 256) * 128;   // 147456
    const int smem2 = NSTG * (128 + 128) * 128;   //  98304
    cudaFuncSetAttribute((const void*)gemm_h<256, 512, 1, true>,
                         cudaFuncAttributeMaxDynamicSharedMemorySize, smem1);
    cudaFuncSetAttribute((const void*)gemm_h<128, 256, 2, false>,
                         cudaFuncAttributeMaxDynamicSharedMemorySize, smem2);

    const float inv_scale = 1.0f / sqrtf((float)SEQ);
    const int n4 = BATCH * SEQ * DIM / 4;

    // 1) convert Q, K to fp16
    to_half_qk_kernel<<<dim3((n4 + 255) / 256, 2), 256>>>(
        (const float4*)q, (const float4*)k, (__half2*)qh, (__half2*)kh, n4);

    // 2) GEMM1 + transpose peers: x<8 -> E = exp(Q K^T * a) + partials;
    //    x==8 -> V[., m0..m0+128, :] -> Vt (fp16), hidden under tensor work.
    dim3 g1(SEQ / 256 + 1, SEQ / 128, BATCH);
    gemm_h<256, 512, 1, true><<<g1, 512, smem1>>>(qh, kh, wh, part, nullptr,
                                                  v, vt, SEQ, SEQ, DIM, inv_scale);

    // 3) GEMM2 + normalize peers: x<4 -> out = (E V)*inv ; x>=4 -> W = E*inv.
    dim3 g2(DIM / 128 + 2, SEQ / 128, BATCH);
    gemm_h<128, 256, 2, false><<<g2, 256, smem2>>>(wh, vt, out, part, w,
                                                   nullptr, nullptr,
                                                   SEQ, DIM, SEQ, 1.0f);
}

// round 15
// speedup vs baseline: 1.0319x; 1.0319x over previous
#include <cuda_runtime.h>
#include <cuda_fp16.h>
#include <cstdint>
#include <math.h>

// Problem constants: q,k,v : [B, S, D] float32
#define BATCH 8
#define SEQ   2048
#define DIM   512
#define NROWS (BATCH * SEQ)        // 16384
#define NTILE 8                    // SEQ / 256 (GEMM1 n-tiles per row)

// ---------------------------------------------------------------------------
// Scratch (__device__ globals; no allocation allowed)
// ---------------------------------------------------------------------------
__device__ __half g_qh[(size_t)BATCH * SEQ * DIM];   // Q in fp16
__device__ __half g_kh[(size_t)BATCH * SEQ * DIM];   // K in fp16
__device__ __half g_vt[(size_t)BATCH * DIM * SEQ];   // V transposed (K-major), fp16
__device__ __half g_wh[(size_t)BATCH * SEQ * SEQ];   // E = exp(scores), fp16
__device__ float  g_part[(size_t)NTILE * NROWS];     // per-CTA row partial sums

__device__ __forceinline__ void ldsm_x4(uint32_t r[4], uint32_t addr) {
    asm volatile("ldmatrix.sync.aligned.m8n8.x4.shared.b16 {%0,%1,%2,%3}, [%4];"
                 : "=r"(r[0]), "=r"(r[1]), "=r"(r[2]), "=r"(r[3]) : "r"(addr));
}

// ---------------------------------------------------------------------------
// fp16 warp-MMA GEMM:  C[b] = A[b] (MxK, K-major) * B[b]^T (NxK, K-major)
// BM=128 fixed; TBN/TNTHR templated. BK=64 halves (128B rows, XOR swizzle),
// 3-stage cp.async, warp tile 64x32 (wm = wid&1, wn = wid>>1).
// EXP_OUT=true : store fp16 exp(alpha*acc), emit per-CTA row partial sums to
//                part[nTile][B*S]. (GEMM1: E = exp(scores))
// EXP_OUT=false: GEMM2. grid.x = DIM/TBN + 1. CTAs with blockIdx.x < DIM/TBN
//                run the GEMM (out = E V * inv, inv recomputed from part in
//                the epilogue — deterministic). CTAs with x == DIM/TBN are
//                NORMALIZE peers: skip the mainloop, stream fp32 W = E * inv
//                for their 128-row block (same kernel => co-residency; short
//                memory CTAs pack into slots left over by long tensor CTAs).
// ---------------------------------------------------------------------------
#define NSTG 3

template <int TBN, int TNTHR, int MINB, bool EXP_OUT>
__global__ __launch_bounds__(TNTHR, MINB)
void gemm_h(const __half* __restrict__ A, const __half* __restrict__ B,
            void* __restrict__ Cv, float* __restrict__ part,
            float* __restrict__ Wout,
            int M, int N, int Kd, float alpha)
{
    constexpr int A_BYTES = 128 * 128;
    constexpr int B_BYTES = TBN * 128;
    constexpr int STAGE_BYTES = A_BYTES + B_BYTES;
    constexpr int AI = (128 * 8) / TNTHR;
    constexpr int BI = (TBN * 8) / TNTHR;
    constexpr int NWN = TNTHR / 64;          // warps in n-direction

    extern __shared__ char smem[];
    const uint32_t smem_b = (uint32_t)__cvta_generic_to_shared(smem);

    const int tid  = threadIdx.x;
    const int bz = blockIdx.z;
    const int m0 = blockIdx.y * 128;
    const size_t grow0 = (size_t)bz * M + m0;       // first global row

    // ---- Normalize peer path (GEMM2 only, blockIdx.x == gridDim.x-1) ----
    if (!EXP_OUT && blockIdx.x == gridDim.x - 1) {
        __shared__ float s_inv[128];
        if (tid < 128) {
            float s = 0.0f;
#pragma unroll
            for (int j = 0; j < NTILE; j++)
                s += __ldg(part + (size_t)j * NROWS + grow0 + tid);
            s_inv[tid] = 1.0f / s;
        }
        __syncthreads();
        // W[row] = E[row] * inv for rows grow0..grow0+127 (E row len = Kd).
#pragma unroll 2
        for (int ch = tid; ch < 128 * 256; ch += TNTHR) {
            const int r  = ch >> 8;          // 0..127
            const int cc = ch & 255;         // 16B chunk in row
            const float iv = s_inv[r];
            float4 raw = __ldg(reinterpret_cast<const float4*>(
                                   A + (grow0 + r) * (size_t)Kd) + cc);
            float2 p0 = __half22float2(*reinterpret_cast<__half2*>(&raw.x));
            float2 p1 = __half22float2(*reinterpret_cast<__half2*>(&raw.y));
            float2 p2 = __half22float2(*reinterpret_cast<__half2*>(&raw.z));
            float2 p3 = __half22float2(*reinterpret_cast<__half2*>(&raw.w));
            float4 o0 = make_float4(p0.x * iv, p0.y * iv, p1.x * iv, p1.y * iv);
            float4 o1 = make_float4(p2.x * iv, p2.y * iv, p3.x * iv, p3.y * iv);
            float* pw = Wout + (grow0 + r) * (size_t)Kd + cc * 8;
            __stcs(reinterpret_cast<float4*>(pw), o0);       // never re-read
            __stcs(reinterpret_cast<float4*>(pw + 4), o1);
        }
        return;
    }

    const int wid  = tid >> 5;
    const int lane = tid & 31;
    const int g    = lane >> 2;
    const int tg   = lane & 3;
    const int lr   = lane & 15;
    const int lc   = lane >> 4;

    const int wm = wid & 1;
    const int wn = wid >> 1;

    const int n0 = blockIdx.x * TBN;
    const __half* Ab = A + (size_t)bz * M * Kd;
    const __half* Bb = B + (size_t)bz * N * Kd;

    float acc[4][4][4];
#pragma unroll
    for (int i = 0; i < 4; i++)
#pragma unroll
        for (int j = 0; j < 4; j++)
#pragma unroll
            for (int r = 0; r < 4; r++)
                acc[i][j][r] = 0.0f;

    const int T = Kd / 64;

    auto load_stage = [&](int buf, int kt) {
        const int k0 = kt * 64;
        const uint32_t ab = smem_b + (uint32_t)buf * STAGE_BYTES;
        const uint32_t bb = ab + A_BYTES;
#pragma unroll
        for (int i = 0; i < AI; i++) {
            int idx = tid + i * TNTHR;
            int row = idx >> 3;
            int c   = idx & 7;
            uint32_t d = ab + (uint32_t)(row * 128 + ((c ^ (row & 7)) << 4));
            const __half* s = Ab + (size_t)(m0 + row) * Kd + k0 + c * 8;
            asm volatile("cp.async.cg.shared.global [%0], [%1], 16;" :: "r"(d), "l"(s));
        }
#pragma unroll
        for (int i = 0; i < BI; i++) {
            int idx = tid + i * TNTHR;
            int row = idx >> 3;
            int c   = idx & 7;
            uint32_t d = bb + (uint32_t)(row * 128 + ((c ^ (row & 7)) << 4));
            const __half* s = Bb + (size_t)(n0 + row) * Kd + k0 + c * 8;
            asm volatile("cp.async.cg.shared.global [%0], [%1], 16;" :: "r"(d), "l"(s));
        }
    };

#pragma unroll
    for (int s = 0; s < NSTG - 1; s++) {
        load_stage(s, s);
        asm volatile("cp.async.commit_group;" ::: "memory");
    }

    int cbuf = 0;
    int lbuf = NSTG - 1;
    for (int t = 0; t < T; t++) {
        asm volatile("cp.async.wait_group %0;" :: "n"(NSTG - 2) : "memory");
        __syncthreads();

        const int tn = t + NSTG - 1;
        if (tn < T) load_stage(lbuf, tn);
        asm volatile("cp.async.commit_group;" ::: "memory");
        lbuf = (lbuf + 1 == NSTG) ? 0 : lbuf + 1;

        const uint32_t ab = smem_b + (uint32_t)cbuf * STAGE_BYTES;
        const uint32_t bb = ab + A_BYTES;
        cbuf = (cbuf + 1 == NSTG) ? 0 : cbuf + 1;

#pragma unroll
        for (int ks = 0; ks < 4; ks++) {
            const int c = ks * 2 + lc;
            uint32_t a[4][4], b[2][4];
#pragma unroll
            for (int mt = 0; mt < 4; mt++) {
                int r = wm * 64 + mt * 16 + lr;
                ldsm_x4(a[mt], ab + (uint32_t)(r * 128 + ((c ^ (r & 7)) << 4)));
            }
#pragma unroll
            for (int pr = 0; pr < 2; pr++) {
                int r = wn * 32 + pr * 16 + lr;
                ldsm_x4(b[pr], bb + (uint32_t)(r * 128 + ((c ^ (r & 7)) << 4)));
            }
#pragma unroll
            for (int mt = 0; mt < 4; mt++)
#pragma unroll
                for (int nt = 0; nt < 4; nt++) {
                    const int pr = nt >> 1, od = nt & 1;
                    asm volatile(
                        "mma.sync.aligned.m16n8k16.row.col.f32.f16.f16.f32 "
                        "{%0,%1,%2,%3}, {%4,%5,%6,%7}, {%8,%9}, {%0,%1,%2,%3};"
                        : "+f"(acc[mt][nt][0]), "+f"(acc[mt][nt][1]),
                          "+f"(acc[mt][nt][2]), "+f"(acc[mt][nt][3])
                        : "r"(a[mt][0]), "r"(a[mt][1]), "r"(a[mt][2]), "r"(a[mt][3]),
                          "r"(b[pr][od]), "r"(b[pr][od + 2]));
                }
        }
    }

    if (EXP_OUT) {
        // ---- Epilogue: E = exp(alpha*acc) -> fp16, + row partial sums ----
        __half* Cb = (__half*)Cv + (size_t)bz * M * N;
        __syncthreads();                          // stage smem now dead
        float* ssum = reinterpret_cast<float*>(smem);   // [128][NWN]
#pragma unroll
        for (int mt = 0; mt < 4; mt++) {
            const int row = m0 + wm * 64 + mt * 16 + g;
            float s0 = 0.0f, s1 = 0.0f;
#pragma unroll
            for (int nt = 0; nt < 4; nt++) {
                const int col = n0 + wn * 32 + nt * 8 + 2 * tg;
                float e0 = __expf(acc[mt][nt][0] * alpha);
                float e1 = __expf(acc[mt][nt][1] * alpha);
                float e2 = __expf(acc[mt][nt][2] * alpha);
                float e3 = __expf(acc[mt][nt][3] * alpha);
                *reinterpret_cast<__half2*>(Cb + (size_t)row * N + col) =
                    __float22half2_rn(make_float2(e0, e1));
                *reinterpret_cast<__half2*>(Cb + (size_t)(row + 8) * N + col) =
                    __float22half2_rn(make_float2(e2, e3));
                s0 += e0 + e1;
                s1 += e2 + e3;
            }
            s0 += __shfl_xor_sync(0xffffffffu, s0, 1);
            s0 += __shfl_xor_sync(0xffffffffu, s0, 2);
            s1 += __shfl_xor_sync(0xffffffffu, s1, 1);
            s1 += __shfl_xor_sync(0xffffffffu, s1, 2);
            if (tg == 0) {
                const int rl = wm * 64 + mt * 16 + g;
                ssum[rl * NWN + wn]       = s0;
                ssum[(rl + 8) * NWN + wn] = s1;
            }
        }
        __syncthreads();
        if (tid < 128) {
            float tsum = 0.0f;
#pragma unroll
            for (int j = 0; j < NWN; j++) tsum += ssum[tid * NWN + j];
            part[(size_t)blockIdx.x * NROWS + grow0 + tid] = tsum;
        }
    } else {
        // ---- Epilogue: inv from partials (deterministic), then fp32 out ----
        __syncthreads();                          // stage smem now dead
        float* s_inv = reinterpret_cast<float*>(smem);   // [128]
        if (tid < 128) {
            float s = 0.0f;
#pragma unroll
            for (int j = 0; j < NTILE; j++)
                s += __ldg(part + (size_t)j * NROWS + grow0 + tid);
            s_inv[tid] = 1.0f / s;
        }
        __syncthreads();

        float* Cb = (float*)Cv + (size_t)bz * M * N;
#pragma unroll
        for (int mt = 0; mt < 4; mt++) {
            const int rl = wm * 64 + mt * 16 + g;
            const int row = m0 + rl;
            const float i0 = s_inv[rl] * alpha;
            const float i1 = s_inv[rl + 8] * alpha;
#pragma unroll
            for (int nt = 0; nt < 4; nt++) {
                const int col = n0 + wn * 32 + nt * 8 + 2 * tg;
                float2 lo, hi;
                lo.x = acc[mt][nt][0] * i0; lo.y = acc[mt][nt][1] * i0;
                hi.x = acc[mt][nt][2] * i1; hi.y = acc[mt][nt][3] * i1;
                __stcs(reinterpret_cast<float2*>(Cb + (size_t)row * N + col), lo);
                __stcs(reinterpret_cast<float2*>(Cb + (size_t)(row + 8) * N + col), hi);
            }
        }
    }
}

// ---------------------------------------------------------------------------
// Fused prep (one launch, heterogeneous CTAs):
//   x < 8192  : convert Q and K fp32 -> fp16 (one float4 each per thread)
//   x >= 8192 : transpose V 32x32 tile fp32 -> fp16 into Vt [B, D, S]
// ---------------------------------------------------------------------------
#define PREP_CONV_CTAS 8192        // 8192*256 threads = 2,097,152 float4 units
#define PREP_TRAN_CTAS 8192        // (2048/32)*(512/32)*8 tiles
__global__ __launch_bounds__(256)
void prep_kernel(const float4* __restrict__ q, const float4* __restrict__ k,
                 __half2* __restrict__ qh, __half2* __restrict__ kh,
                 const float* __restrict__ V, __half* __restrict__ Vt)
{
    const int tid = threadIdx.x;
    if (blockIdx.x < PREP_CONV_CTAS) {
        const int u = blockIdx.x * 256 + tid;      // float4 index
        float4 a = q[u];
        qh[2 * u]     = __float22half2_rn(make_float2(a.x, a.y));
        qh[2 * u + 1] = __float22half2_rn(make_float2(a.z, a.w));
        float4 b = k[u];
        kh[2 * u]     = __float22half2_rn(make_float2(b.x, b.y));
        kh[2 * u + 1] = __float22half2_rn(make_float2(b.z, b.w));
    } else {
        __shared__ float tile[32][33];
        const int t  = blockIdx.x - PREP_CONV_CTAS;
        const int b  = t >> 10;                    // 1024 tiles per batch
        const int tt = t & 1023;
        const int s0 = (tt >> 4) * 32;
        const int d0 = (tt & 15) * 32;
        const float* Vb = V  + (size_t)b * SEQ * DIM;
        __half*      Tb = Vt + (size_t)b * DIM * SEQ;
        const int xx = tid & 31;
        const int yy = tid >> 5;                   // 0..7
#pragma unroll
        for (int i = 0; i < 32; i += 8)
            tile[yy + i][xx] = Vb[(size_t)(s0 + yy + i) * DIM + d0 + xx];
        __syncthreads();
#pragma unroll
        for (int i = 0; i < 32; i += 8)
            Tb[(size_t)(d0 + yy + i) * SEQ + s0 + xx] =
                __float2half_rn(tile[xx][yy + i]);
    }
}

// ---------------------------------------------------------------------------
// Launch: out = [output (B*S*D) | attention_weights (B*S*S)]
// ---------------------------------------------------------------------------
extern "C" void kernel_launch(void* const* d_in, const int* in_sizes, int n_in,
                              void* d_out, int out_size)
{
    (void)in_sizes; (void)n_in; (void)out_size;
    const float* q = (const float*)d_in[0];
    const float* k = (const float*)d_in[1];
    const float* v = (const float*)d_in[2];
    float* out = (float*)d_out;
    float* w   = out + (size_t)BATCH * SEQ * DIM;   // fp32 weights region

    __half *qh, *kh, *vt, *wh;
    float *part;
    cudaGetSymbolAddress((void**)&qh, g_qh);
    cudaGetSymbolAddress((void**)&kh, g_kh);
    cudaGetSymbolAddress((void**)&vt, g_vt);
    cudaGetSymbolAddress((void**)&wh, g_wh);
    cudaGetSymbolAddress((void**)&part, g_part);

    const int smem1 = NSTG * (128 + 256) * 128;   // 147456
    const int smem2 = NSTG * (128 + 128) * 128;   //  98304
    cudaFuncSetAttribute((const void*)gemm_h<256, 512, 1, true>,
                         cudaFuncAttributeMaxDynamicSharedMemorySize, smem1);
    cudaFuncSetAttribute((const void*)gemm_h<128, 256, 2, false>,
                         cudaFuncAttributeMaxDynamicSharedMemorySize, smem2);

    const float inv_scale = 1.0f / sqrtf((float)SEQ);

    // 1) fused prep: Q/K fp16 convert + V transpose (one kernel)
    prep_kernel<<<PREP_CONV_CTAS + PREP_TRAN_CTAS, 256>>>(
        (const float4*)q, (const float4*)k, (__half2*)qh, (__half2*)kh, v, vt);

    // 2) E = exp(Q K^T / sqrt(S)) -> g_wh (fp16) + row partial sums
    dim3 g1(SEQ / 256, SEQ / 128, BATCH);
    gemm_h<256, 512, 1, true><<<g1, 512, smem1>>>(qh, kh, wh, part, nullptr,
                                                  SEQ, SEQ, DIM, inv_scale);

    // 3) combined kernel: x<4 -> out = (E V)*inv ; x==4 -> W = E*inv (fp32)
    dim3 g2(DIM / 128 + 1, SEQ / 128, BATCH);
    gemm_h<128, 256, 2, false><<<g2, 256, smem2>>>(wh, vt, out, part, w,
                                                   SEQ, DIM, SEQ, 1.0f);
}